// round 8
// baseline (speedup 1.0000x reference)
#include <cuda_runtime.h>
#include <cuda_bf16.h>

#define DINL __device__ __forceinline__

// ---------------------------------------------------------------------------
// Packed f32x2 helpers (Blackwell FFMA2 path)
// ---------------------------------------------------------------------------
typedef unsigned long long u64;

DINL u64 ffma2u(u64 a, u64 b, u64 c) {
    u64 d;
    asm("fma.rn.f32x2 %0, %1, %2, %3;" : "=l"(d) : "l"(a), "l"(b), "l"(c));
    return d;
}
DINL u64 add2(u64 a, u64 b) {
    u64 d;
    asm("add.rn.f32x2 %0, %1, %2;" : "=l"(d) : "l"(a), "l"(b));
    return d;
}
DINL u64 pack2(float a, float b) {
    u64 u; asm("mov.b64 %0, {%1, %2};" : "=l"(u) : "f"(a), "f"(b)); return u;
}
DINL u64 packdup(float a) {
    u64 u; asm("mov.b64 %0, {%1, %1};" : "=l"(u) : "f"(a)); return u;
}
DINL float2 unpk(u64 u) {
    float2 v; asm("mov.b64 {%0, %1}, %2;" : "=f"(v.x), "=f"(v.y) : "l"(u)); return v;
}
DINL float sig_(float x)  { return __fdividef(1.f, 1.f + __expf(-x)); }
DINL float tanh_(float x) { return __fdividef(2.f, 1.f + __expf(-2.f * x)) - 1.f; }

// ---------------------------------------------------------------------------
// Device-global scratch (no allocation allowed)
// ---------------------------------------------------------------------------
__device__ float4 d_WT4_e1[32 * 512];    // Whh_e1 transposed: [k4][g] float4 over k
__device__ float  d_bias_e1[512];        // bih_e1 + bhh_e1
__device__ float4 d_WT4_d1[32 * 512];    // Whh_d1 transposed
__device__ float  d_bias_d1[512];
__device__ float  d_WihT_e2[128 * 256];  // Wih_e2 transposed [k][g]
__device__ float  d_bias_e2[256];
__device__ float  d_h1[4096 * 128];      // e1 final hidden per batch element
__device__ float  d_pre2[4096 * 256];    // e2 input projection + bias
__device__ float  d_zvec[64];            // e2 final hidden

// ---------------------------------------------------------------------------
// K0: weight transposes / bias folding
// ---------------------------------------------------------------------------
__global__ void k0_prep(const float* __restrict__ Whh_e1,
                        const float* __restrict__ bih_e1, const float* __restrict__ bhh_e1,
                        const float* __restrict__ Wih_e2,
                        const float* __restrict__ bih_e2, const float* __restrict__ bhh_e2,
                        const float* __restrict__ Whh_d1,
                        const float* __restrict__ bih_d1, const float* __restrict__ bhh_d1) {
    int stride = gridDim.x * blockDim.x;
    int tid0 = blockIdx.x * blockDim.x + threadIdx.x;
    for (int i = tid0; i < 32 * 512; i += stride) {
        int k4 = i >> 9, g = i & 511;
        const float* r1 = Whh_e1 + g * 128 + 4 * k4;
        d_WT4_e1[i] = make_float4(r1[0], r1[1], r1[2], r1[3]);
        const float* r2 = Whh_d1 + g * 128 + 4 * k4;
        d_WT4_d1[i] = make_float4(r2[0], r2[1], r2[2], r2[3]);
    }
    for (int i = tid0; i < 512; i += stride) {
        d_bias_e1[i] = bih_e1[i] + bhh_e1[i];
        d_bias_d1[i] = bih_d1[i] + bhh_d1[i];
    }
    for (int i = tid0; i < 128 * 256; i += stride) {
        int k = i >> 8, g = i & 255;
        d_WihT_e2[i] = Wih_e2[g * 128 + k];
    }
    for (int i = tid0; i < 256; i += stride) d_bias_e2[i] = bih_e2[i] + bhh_e2[i];
}

// ---------------------------------------------------------------------------
// K1: encoder LSTM 1.  147 blocks x 512 threads, 28 batch elems per block.
// Thread g owns gate row g for all 28 elems; h broadcast from SMEM; FFMA2
// over batch pairs; weights streamed coalesced (float4 transposed layout).
// ---------------------------------------------------------------------------
#define K1_NB 28
__global__ __launch_bounds__(512, 1) void k1_e1(const float* __restrict__ x,
                                                const float* __restrict__ Wih_e1) {
    extern __shared__ float sm[];
    float* xs  = sm;                   // [28][140]
    float* hs  = sm + K1_NB * 140;     // [128][30]  (padded rows; 8B aligned)
    float* gsh = hs + 128 * 30;        // [512][29]  (pad 29 -> conflict-free)
    const int g = threadIdx.x;
    const int base = blockIdx.x * K1_NB;
    int nb = 4096 - base; if (nb > K1_NB) nb = K1_NB;

    for (int i = g; i < K1_NB * 140; i += 512) {
        int b = i / 140, tt = i - b * 140;
        xs[i] = (b < nb) ? x[(base + b) * 140 + tt] : 0.f;
    }
    for (int i = g; i < 128 * 30; i += 512) hs[i] = 0.f;
    float c[K1_NB];
#pragma unroll
    for (int b = 0; b < K1_NB; ++b) c[b] = 0.f;

    const float wih  = Wih_e1[g];
    const float bias = d_bias_e1[g];
    const bool  is_t = (g >= 256 && g < 384);   // tanh for the 'g' gate
    const float4* __restrict__ Wp = d_WT4_e1 + g;
    const u64* hs2 = (const u64*)hs;
    __syncthreads();

    for (int t = 0; t < 140; ++t) {
        u64 acc[14];
#pragma unroll
        for (int bp = 0; bp < 14; ++bp) {
            acc[bp] = pack2(fmaf(wih, xs[(2 * bp) * 140 + t], bias),
                            fmaf(wih, xs[(2 * bp + 1) * 140 + t], bias));
        }
#pragma unroll 4
        for (int k4 = 0; k4 < 32; ++k4) {
            float4 w = Wp[(size_t)k4 * 512];
            const u64* hk = hs2 + (4 * k4) * 15;
            u64 wd;
            wd = packdup(w.x);
#pragma unroll
            for (int bp = 0; bp < 14; ++bp) acc[bp] = ffma2u(wd, hk[bp], acc[bp]);
            wd = packdup(w.y);
#pragma unroll
            for (int bp = 0; bp < 14; ++bp) acc[bp] = ffma2u(wd, hk[15 + bp], acc[bp]);
            wd = packdup(w.z);
#pragma unroll
            for (int bp = 0; bp < 14; ++bp) acc[bp] = ffma2u(wd, hk[30 + bp], acc[bp]);
            wd = packdup(w.w);
#pragma unroll
            for (int bp = 0; bp < 14; ++bp) acc[bp] = ffma2u(wd, hk[45 + bp], acc[bp]);
        }
#pragma unroll
        for (int bp = 0; bp < 14; ++bp) {
            float2 v = unpk(acc[bp]);
            float a0 = is_t ? tanh_(v.x) : sig_(v.x);
            float a1 = is_t ? tanh_(v.y) : sig_(v.y);
            gsh[g * 29 + 2 * bp]     = a0;
            gsh[g * 29 + 2 * bp + 1] = a1;
        }
        __syncthreads();
        if (g < 128) {
#pragma unroll
            for (int b = 0; b < K1_NB; ++b) {
                float iv = gsh[g * 29 + b];
                float fv = gsh[(128 + g) * 29 + b];
                float gv = gsh[(256 + g) * 29 + b];
                float ov = gsh[(384 + g) * 29 + b];
                float cc = fmaf(fv, c[b], iv * gv);
                c[b] = cc;
                hs[g * 30 + b] = ov * tanh_(cc);
            }
        }
        __syncthreads();
    }
    if (g < 128) {
        for (int b = 0; b < nb; ++b) d_h1[(base + b) * 128 + g] = hs[g * 30 + b];
    }
}
#define K1_SMEM ((K1_NB * 140 + 128 * 30 + 512 * 29) * 4)

// ---------------------------------------------------------------------------
// K2: e2 input projection  pre2[t][g] = h1[t] . Wih_e2[g] + (bih+bhh)
// ---------------------------------------------------------------------------
__global__ __launch_bounds__(256, 1) void k2_proj() {
    __shared__ float hsm[32 * 128];
    const int g = threadIdx.x;
    const int t0 = blockIdx.x * 32;
    for (int i = g; i < 32 * 128; i += 256) hsm[i] = d_h1[t0 * 128 + i];
    __syncthreads();
    float acc[32];
#pragma unroll
    for (int r = 0; r < 32; ++r) acc[r] = 0.f;
    for (int k = 0; k < 128; ++k) {
        float w = d_WihT_e2[k * 256 + g];
#pragma unroll
        for (int r = 0; r < 32; ++r) acc[r] = fmaf(hsm[r * 128 + k], w, acc[r]);
    }
    float b = d_bias_e2[g];
#pragma unroll
    for (int r = 0; r < 32; ++r) d_pre2[(t0 + r) * 256 + g] = acc[r] + b;
}

// ---------------------------------------------------------------------------
// K3: e2 serial scan. 1 block, 256 threads, 4096 steps, H=64.
// Weights in registers; h broadcast from SMEM; pre prefetched 1 step ahead.
// ---------------------------------------------------------------------------
__global__ __launch_bounds__(256, 1) void k3_e2(const float* __restrict__ Whh_e2) {
    __shared__ float h_sh[64];
    __shared__ float gsh[256];
    const int g = threadIdx.x;
    u64 w2[32];
    const u64* Wrow = ((const u64*)Whh_e2) + g * 32;
#pragma unroll
    for (int k = 0; k < 32; ++k) w2[k] = Wrow[k];
    if (g < 64) h_sh[g] = 0.f;
    float c = 0.f;
    const bool is_t = ((g >> 6) == 2);
    float pre_cur = d_pre2[g];           // t = 0
    __syncthreads();
    const u64* hs2 = (const u64*)h_sh;
    for (int t = 0; t < 4096; ++t) {
        float pre_nxt = (t < 4095) ? d_pre2[(t + 1) * 256 + g] : 0.f;
        u64 a0 = 0, a1 = 0, a2 = 0, a3 = 0;
#pragma unroll
        for (int k = 0; k < 32; k += 4) {
            a0 = ffma2u(w2[k],     hs2[k],     a0);
            a1 = ffma2u(w2[k + 1], hs2[k + 1], a1);
            a2 = ffma2u(w2[k + 2], hs2[k + 2], a2);
            a3 = ffma2u(w2[k + 3], hs2[k + 3], a3);
        }
        a0 = add2(a0, a1); a2 = add2(a2, a3); a0 = add2(a0, a2);
        float2 v = unpk(a0);
        float xv = v.x + v.y + pre_cur;
        gsh[g] = is_t ? tanh_(xv) : sig_(xv);
        __syncthreads();
        if (g < 64) {
            float iv = gsh[g], fv = gsh[64 + g], gv = gsh[128 + g], ov = gsh[192 + g];
            c = fmaf(fv, c, iv * gv);
            h_sh[g] = ov * tanh_(c);
        }
        __syncthreads();
        pre_cur = pre_nxt;
    }
    if (g < 64) d_zvec[g] = h_sh[g];
}

// ---------------------------------------------------------------------------
// K4: decoder (d1 H=128 + fused d2 H=1). 1 block, 512 threads, 140 steps.
// ---------------------------------------------------------------------------
__global__ __launch_bounds__(512, 1) void k4_dec(const float* __restrict__ Wih_d1,
                                                 const float* __restrict__ Wih_d2,
                                                 const float* __restrict__ Whh_d2,
                                                 const float* __restrict__ bih_d2,
                                                 const float* __restrict__ bhh_d2,
                                                 float* __restrict__ out) {
    __shared__ float zsh[64];
    __shared__ float h_sh[128];
    __shared__ float gsh[512];
    const int g = threadIdx.x;
    if (g < 64)  zsh[g] = d_zvec[g];
    if (g < 128) h_sh[g] = 0.f;
    __syncthreads();
    float wz = d_bias_d1[g];
#pragma unroll 8
    for (int k = 0; k < 64; ++k) wz = fmaf(Wih_d1[g * 64 + k], zsh[k], wz);
    const bool is_t = (g >= 256 && g < 384);
    float c = 0.f;

    // warp-0 d2 state
    float wd2[16], b2[4], wh[4];
    float c2 = 0.f, h2 = 0.f;
    if (g < 32) {
#pragma unroll
        for (int q = 0; q < 4; ++q) {
#pragma unroll
            for (int m = 0; m < 4; ++m) wd2[q * 4 + m] = Wih_d2[q * 128 + m * 32 + g];
            b2[q] = bih_d2[q] + bhh_d2[q];
            wh[q] = Whh_d2[q];
        }
    }
    const float4* __restrict__ Wp = d_WT4_d1 + g;
    const u64* hs2 = (const u64*)h_sh;

    for (int t = 0; t < 140; ++t) {
        u64 a0 = 0, a1 = 0;
#pragma unroll 8
        for (int k4 = 0; k4 < 32; ++k4) {
            float4 w = Wp[(size_t)k4 * 512];
            a0 = ffma2u(pack2(w.x, w.y), hs2[2 * k4], a0);
            a1 = ffma2u(pack2(w.z, w.w), hs2[2 * k4 + 1], a1);
        }
        a0 = add2(a0, a1);
        float2 v = unpk(a0);
        float xv = v.x + v.y + wz;
        gsh[g] = is_t ? tanh_(xv) : sig_(xv);
        __syncthreads();
        if (g < 128) {
            float iv = gsh[g], fv = gsh[128 + g], gv = gsh[256 + g], ov = gsh[384 + g];
            c = fmaf(fv, c, iv * gv);
            h_sh[g] = ov * tanh_(c);
        }
        __syncthreads();
        if (g < 32) {
            float p0 = 0.f, p1 = 0.f, p2 = 0.f, p3 = 0.f;
#pragma unroll
            for (int m = 0; m < 4; ++m) {
                float hv = h_sh[m * 32 + g];
                p0 = fmaf(wd2[0 * 4 + m], hv, p0);
                p1 = fmaf(wd2[1 * 4 + m], hv, p1);
                p2 = fmaf(wd2[2 * 4 + m], hv, p2);
                p3 = fmaf(wd2[3 * 4 + m], hv, p3);
            }
#pragma unroll
            for (int off = 16; off > 0; off >>= 1) {
                p0 += __shfl_xor_sync(0xffffffffu, p0, off);
                p1 += __shfl_xor_sync(0xffffffffu, p1, off);
                p2 += __shfl_xor_sync(0xffffffffu, p2, off);
                p3 += __shfl_xor_sync(0xffffffffu, p3, off);
            }
            float iv2 = sig_(p0 + b2[0] + wh[0] * h2);
            float fv2 = sig_(p1 + b2[1] + wh[1] * h2);
            float gv2 = tanh_(p2 + b2[2] + wh[2] * h2);
            float ov2 = sig_(p3 + b2[3] + wh[3] * h2);
            c2 = fmaf(fv2, c2, iv2 * gv2);
            h2 = ov2 * tanh_(c2);
            if (g == 0) out[t] = h2;
        }
    }
}

// ---------------------------------------------------------------------------
// Launch
// ---------------------------------------------------------------------------
extern "C" void kernel_launch(void* const* d_in, const int* in_sizes, int n_in,
                              void* d_out, int out_size) {
    const float* x      = (const float*)d_in[0];
    const float* Wih_e1 = (const float*)d_in[1];
    const float* Whh_e1 = (const float*)d_in[2];
    const float* bih_e1 = (const float*)d_in[3];
    const float* bhh_e1 = (const float*)d_in[4];
    const float* Wih_e2 = (const float*)d_in[5];
    const float* Whh_e2 = (const float*)d_in[6];
    const float* bih_e2 = (const float*)d_in[7];
    const float* bhh_e2 = (const float*)d_in[8];
    const float* Wih_d1 = (const float*)d_in[9];
    const float* Whh_d1 = (const float*)d_in[10];
    const float* bih_d1 = (const float*)d_in[11];
    const float* bhh_d1 = (const float*)d_in[12];
    const float* Wih_d2 = (const float*)d_in[13];
    const float* Whh_d2 = (const float*)d_in[14];
    const float* bih_d2 = (const float*)d_in[15];
    const float* bhh_d2 = (const float*)d_in[16];
    float* out = (float*)d_out;
    (void)in_sizes; (void)n_in; (void)out_size;

    cudaFuncSetAttribute(k1_e1, cudaFuncAttributeMaxDynamicSharedMemorySize, K1_SMEM);

    k0_prep<<<64, 256>>>(Whh_e1, bih_e1, bhh_e1, Wih_e2, bih_e2, bhh_e2,
                         Whh_d1, bih_d1, bhh_d1);
    k1_e1<<<147, 512, K1_SMEM>>>(x, Wih_e1);
    k2_proj<<<128, 256>>>();
    k3_e2<<<1, 256>>>(Whh_e2);
    k4_dec<<<1, 512>>>(Wih_d1, Wih_d2, Whh_d2, bih_d2, bhh_d2, out);
}